// round 16
// baseline (speedup 1.0000x reference)
#include <cuda_runtime.h>
#include <cuda_bf16.h>
#include <math.h>
#include <cstdint>

#define BB 32
#define NN 1024
#define CC 192
#define HH 3
#define DD 64

// Scratch (device globals — allocation-free)
__device__ __align__(16) __nv_bfloat16 g_Qb [BB*HH*NN*DD];  // [bh][n][d], pre-scaled by 0.125/tau(b,h)
__device__ __align__(16) __nv_bfloat16 g_Kb [BB*HH*NN*DD];  // [bh][n][d]
__device__ __align__(16) __nv_bfloat16 g_Vtb[BB*HH*DD*NN];  // [bh][d][n]
__device__ __align__(16) __nv_bfloat16 g_Ob [BB*NN*CC];     // attn out bf16
__device__ float g_conf[BB];

// ───────────────────────── helpers ─────────────────────────
__device__ __forceinline__ uint32_t smem_u32(const void* p) {
    uint32_t a;
    asm("{ .reg .u64 t; cvta.to.shared.u64 t, %1; cvt.u32.u64 %0, t; }" : "=r"(a) : "l"(p));
    return a;
}
#define SWZ(o) ((o) ^ (((o) >> 3) & 0x70))

#define LDSM4(r0, r1, r2, r3, addr)                                              \
    asm volatile("ldmatrix.sync.aligned.m8n8.x4.shared.b16 {%0,%1,%2,%3}, [%4];" \
        : "=r"(r0), "=r"(r1), "=r"(r2), "=r"(r3) : "r"(addr))

#define MMA16816(d, a, b0, b1)                                                   \
    asm volatile("mma.sync.aligned.m16n8k16.row.col.f32.bf16.bf16.f32 "          \
        "{%0,%1,%2,%3}, {%4,%5,%6,%7}, {%8,%9}, {%0,%1,%2,%3};"                  \
        : "+f"((d)[0]), "+f"((d)[1]), "+f"((d)[2]), "+f"((d)[3])                 \
        : "r"((a)[0]), "r"((a)[1]), "r"((a)[2]), "r"((a)[3]), "r"(b0), "r"(b1))

__device__ __forceinline__ void cp16(uint32_t smaddr, const void* g) {
    asm volatile("cp.async.cg.shared.global [%0], [%1], 16;" :: "r"(smaddr), "l"(g));
}
#define CP_COMMIT() asm volatile("cp.async.commit_group;" ::: "memory")
#define CP_WAIT0()  asm volatile("cp.async.wait_group 0;" ::: "memory")

// pack (lo, hi) -> bf16x2
__device__ __forceinline__ uint32_t pack_bf2(float lo, float hi) {
    uint32_t r;
    asm("cvt.rn.satfinite.bf16x2.f32 %0, %1, %2;" : "=r"(r) : "f"(hi), "f"(lo));
    return r;
}

// convert fp32x8 (two float4) -> uint4 of bf16x2
__device__ __forceinline__ uint4 cvt8_bf16(const float* src) {
    float4 a = *(const float4*)src;
    float4 b = *(const float4*)(src + 4);
    uint4 o = { pack_bf2(a.x, a.y), pack_bf2(a.z, a.w),
                pack_bf2(b.x, b.y), pack_bf2(b.z, b.w) };
    return o;
}

// 5th-order Taylor exp (fp32) — for the confidence numerator only
__device__ __forceinline__ float expp(float x) {
    float t = fmaf(x, 8.3333333e-3f, 4.1666667e-2f);
    t = fmaf(x, t, 1.6666667e-1f);
    t = fmaf(x, t, 0.5f);
    t = fmaf(x, t, 1.0f);
    t = fmaf(x, t, 1.0f);
    return t;
}

// 4th-order Taylor exp on a bf16x2 pair (|x| <~ 0.5).
#define K_1_24 0x3D2B3D2Bu
#define K_1_6  0x3E2B3E2Bu
#define K_HALF 0x3F003F00u
#define K_ONE  0x3F803F80u
__device__ __forceinline__ uint32_t exp_pair(uint32_t x) {
    uint32_t t;
    const uint32_t k24 = K_1_24, k6 = K_1_6, kh = K_HALF, k1 = K_ONE;
    asm("fma.rn.bf16x2 %0, %1, %2, %3;" : "=r"(t) : "r"(x), "r"(k24), "r"(k6));
    asm("fma.rn.bf16x2 %0, %1, %2, %3;" : "=r"(t) : "r"(x), "r"(t), "r"(kh));
    asm("fma.rn.bf16x2 %0, %1, %2, %3;" : "=r"(t) : "r"(x), "r"(t), "r"(k1));
    asm("fma.rn.bf16x2 %0, %1, %2, %3;" : "=r"(t) : "r"(x), "r"(t), "r"(k1));
    return t;
}

// ---------------------------------------------------------------------------
// Kernel 1: persistent-A QKV GEMM via HMMA. One CTA = one 128-row m-tile with
// A (x, full K=192, bf16) resident in smem; loops over all 9 column-tiles with
// double-buffered B (one sync per c-iter). Grid = 256 CTAs = one wave @2/SM.
// A layout: 3 K-blocks of [128 rows][128B] SW128. B: 2 bufs of 3x[64][128B].
// Dynamic smem: 49152 (A) + 2*24576 (B) = 98304 bytes.
// ---------------------------------------------------------------------------
__global__ __launch_bounds__(256, 2) void qkv_kernel(const float* __restrict__ x,
                                                     const float* __restrict__ qw,
                                                     const float* __restrict__ bias,
                                                     const float* __restrict__ temp_param,
                                                     const float* __restrict__ tau_al)
{
    extern __shared__ char smem[];
    char* smA  = smem;                   // 3 * 16384
    char* smBb[2] = { smem + 49152, smem + 49152 + 24576 };

    const int t = threadIdx.x, warp = t >> 5, lane = t & 31;
    const int m0 = blockIdx.x * 128;
    const int lr = lane & 7, mm = lane >> 3;
    const uint32_t sAu = smem_u32(smA);
    const uint32_t sBu[2] = { smem_u32(smBb[0]), smem_u32(smBb[1]) };

    if (blockIdx.x == 0 && t < BB) g_conf[t] = 0.0f;

    // B per-thread unit coords (6 units of 8 elems; row = u/24, c8 = u%24)
    int  bsrc[6];
    uint32_t bdst[6];
#pragma unroll
    for (int s = 0; s < 6; s++) {
        int u = t + s*256;
        int row = u / 24, c8 = u - row*24;
        bsrc[s] = row*192 + c8*8;
        bdst[s] = (uint32_t)((c8 >> 3)*8192 + SWZ(row*128 + (c8 & 7)*16));
    }

    // Load A (128 x 192 fp32 -> bf16, 3 K-blocks) — once for the whole kernel
#pragma unroll
    for (int s = 0; s < 12; s++) {
        int u = t + s*256;
        int row = u / 24, c8 = u - row*24;
        *(uint4*)(smA + (c8 >> 3)*16384 + SWZ(row*128 + (c8 & 7)*16)) =
            cvt8_bf16(x + (size_t)(m0 + row)*192 + c8*8);
    }
    // Load B for c-tile 0 into buf 0
#pragma unroll
    for (int s = 0; s < 6; s++)
        *(uint4*)(smBb[0] + bdst[s]) = cvt8_bf16(qw + bsrc[s]);
    __syncthreads();

    const int arow = warp*16 + (mm & 1)*8 + lr, acb = (mm >> 1)*16;
    const int brow = (mm >> 1)*8 + lr,          bcb = (mm & 1)*16;
    const int r = lane >> 2, cb = (lane & 3)*2;
    const int mA = m0 + warp*16 + r;
    const int b = m0 >> 10;               // single batch per CTA
    const int n = mA & 1023;

    float of[8][4];
#pragma unroll
    for (int i = 0; i < 8; i++)
#pragma unroll
        for (int j = 0; j < 4; j++) of[i][j] = 0.0f;

#pragma unroll 1
    for (int ci = 0; ci < 9; ci++) {
        const int buf = ci & 1;
        const uint32_t sBcur = sBu[buf];

        // issue next c-tile's B LDGs early (latency hides under MMAs)
        uint4 stB[6];
        if (ci < 8) {
            const float* src = qw + (size_t)(ci + 1)*64*192;
#pragma unroll
            for (int s = 0; s < 6; s++) stB[s] = cvt8_bf16(src + bsrc[s]);
        }

        // ── 128x64x192 MMA block ──
#pragma unroll
        for (int ks = 0; ks < 12; ks++) {
            const int kb = ks >> 2, ksl = ks & 3;
            uint32_t af[4];
            LDSM4(af[0], af[1], af[2], af[3],
                  sAu + kb*16384 + SWZ(arow*128 + ksl*32 + acb));
#pragma unroll
            for (int g = 0; g < 4; g++) {
                uint32_t b0, b1, b2, b3;
                LDSM4(b0, b1, b2, b3,
                      sBcur + kb*8192 + SWZ((g*16 + brow)*128 + ksl*32 + bcb));
                MMA16816(of[2*g],   af, b0, b1);
                MMA16816(of[2*g+1], af, b2, b3);
            }
        }

        // stage next B into the other buffer (its readers synced last iter)
        if (ci < 8) {
#pragma unroll
            for (int s = 0; s < 6; s++) *(uint4*)(smBb[buf ^ 1] + bdst[s]) = stB[s];
        }

        // ── epilogue for this c-tile: bias, bf16, scatter ──
        const int c0 = ci * 64;
        const int jj = (c0 >= 384) ? 2 : (c0 >= 192 ? 1 : 0);
        const int h  = (c0 - jj*192) >> 6;
        const int bh = b*HH + h;

        float scq = 1.0f;
        if (jj == 0) {
            float tp  = temp_param[h];
            float tau = tau_al[b*HH + h] + (0.1f + log1pf(expf(tp))) * 1.5f;
            scq = 0.125f / tau;
        }

#pragma unroll
        for (int nt = 0; nt < 8; nt++) {
            const int d = nt*8 + cb;
            float bz0 = bias[c0 + d], bz1 = bias[c0 + d + 1];
            float v0 = of[nt][0] + bz0, v1 = of[nt][1] + bz1;   // row mA
            float v2 = of[nt][2] + bz0, v3 = of[nt][3] + bz1;   // row mA+8
            if (jj == 0) {
                *(uint32_t*)(g_Qb + ((size_t)(bh<<10) + n    )*64 + d) = pack_bf2(v0*scq, v1*scq);
                *(uint32_t*)(g_Qb + ((size_t)(bh<<10) + n + 8)*64 + d) = pack_bf2(v2*scq, v3*scq);
            } else if (jj == 1) {
                *(uint32_t*)(g_Kb + ((size_t)(bh<<10) + n    )*64 + d) = pack_bf2(v0, v1);
                *(uint32_t*)(g_Kb + ((size_t)(bh<<10) + n + 8)*64 + d) = pack_bf2(v2, v3);
            } else {
                __nv_bfloat16* Vt = g_Vtb + ((size_t)bh << 16);
                Vt[((size_t)(d  )<<10) + n    ] = __float2bfloat16(v0);
                Vt[((size_t)(d+1)<<10) + n    ] = __float2bfloat16(v1);
                Vt[((size_t)(d  )<<10) + n + 8] = __float2bfloat16(v2);
                Vt[((size_t)(d+1)<<10) + n + 8] = __float2bfloat16(v3);
            }
            of[nt][0] = 0.0f; of[nt][1] = 0.0f; of[nt][2] = 0.0f; of[nt][3] = 0.0f;
        }

        if (ci < 8) __syncthreads();
    }
}

// ---------------------------------------------------------------------------
// Kernel 2: flash attention, M=32/warp (4 warps, 128 thr), bf16x2 SIMD softmax.
// 3 CTAs/SM. Unchanged from R13/R15 (best measured config).
// ---------------------------------------------------------------------------
__global__ __launch_bounds__(128, 3) void attn_kernel(const float* __restrict__ dropout_logits)
{
    __shared__ __align__(128) char smQ[128*128];
    __shared__ __align__(128) char smK[2][64*128];
    __shared__ __align__(128) char smV[2][64*128];

    const int t = threadIdx.x, warp = t >> 5, lane = t & 31;
    const int b = blockIdx.z, h = blockIdx.y, q0 = blockIdx.x * 128;
    const int bh = b*HH + h;
    const uint32_t sQ = smem_u32(smQ);
    const uint32_t sK[2] = { smem_u32(smK[0]), smem_u32(smK[1]) };
    const uint32_t sV[2] = { smem_u32(smV[0]), smem_u32(smV[1]) };

    const __nv_bfloat16* Qbh  = g_Qb  + (size_t)bh * NN * DD;
    const __nv_bfloat16* Kbh  = g_Kb  + (size_t)bh * NN * DD;
    const __nv_bfloat16* Vtbh = g_Vtb + (size_t)bh * DD * NN;

    // prefetch chunk 0 into buffer 0
#pragma unroll
    for (int s = 0; s < 4; s++) {
        int idx = t + s*128, row = idx >> 3, j = idx & 7;
        cp16(sK[0] + SWZ(row*128 + j*16), Kbh  + (size_t)row*64 + j*8);
        cp16(sV[0] + SWZ(row*128 + j*16), Vtbh + (size_t)row*NN + j*8);
    }
    CP_COMMIT();

    // Q tile [128 x 64] bf16 -> swizzled smem (plain loads)
#pragma unroll
    for (int i = t; i < 1024; i += 128) {
        int row = i >> 3, j = i & 7;
        *(uint4*)(smQ + SWZ(row*128 + j*16)) = *(const uint4*)(Qbh + (size_t)(q0 + row)*64 + j*8);
    }
    __syncthreads();

    const int lr = lane & 7, mm = lane >> 3;
    uint32_t qf[2][4][4];
#pragma unroll
    for (int mt = 0; mt < 2; mt++) {
        const int qrow = warp*32 + mt*16 + (mm & 1)*8 + lr;
        const int qcb  = (mm >> 1)*16;
#pragma unroll
        for (int ks = 0; ks < 4; ks++)
            LDSM4(qf[mt][ks][0], qf[mt][ks][1], qf[mt][ks][2], qf[mt][ks][3],
                  sQ + SWZ(qrow*128 + ks*32 + qcb));
    }

    float of[2][8][4];
#pragma unroll
    for (int mt = 0; mt < 2; mt++)
#pragma unroll
        for (int i = 0; i < 8; i++)
#pragma unroll
            for (int j = 0; j < 4; j++) of[mt][i][j] = 0.0f;
    float lC[2][4];                       // ones-MMA accumulator: row sums of P
#pragma unroll
    for (int mt = 0; mt < 2; mt++)
#pragma unroll
        for (int j = 0; j < 4; j++) lC[mt][j] = 0.0f;
    float mac[2][2] = {{-1e30f,-1e30f},{-1e30f,-1e30f}};

    const int brow = (mm >> 1)*8 + lr;
    const int bcb  = (mm & 1)*16;
    const uint32_t ONES = K_ONE;          // bf16x2 {1.0, 1.0}

    for (int kc = 0; kc < 16; kc++) {
        const int buf = kc & 1;
        CP_WAIT0();
        __syncthreads();

        if (kc < 15) {
            const int n1 = (kc + 1) * 64;
            const uint32_t kb = sK[buf ^ 1], vb = sV[buf ^ 1];
#pragma unroll
            for (int s = 0; s < 4; s++) {
                int idx = t + s*128, row = idx >> 3, j = idx & 7;
                cp16(kb + SWZ(row*128 + j*16), Kbh  + (size_t)(n1 + row)*64 + j*8);
                cp16(vb + SWZ(row*128 + j*16), Vtbh + (size_t)row*NN + n1 + j*8);
            }
            CP_COMMIT();
        }

        const uint32_t sKb = sK[buf], sVb = sV[buf];
#pragma unroll
        for (int g = 0; g < 4; g++) {
            // ── S = Q·K^T (logits pre-scaled), K frags shared across m-tiles ──
            float sa[2][2][4];
#pragma unroll
            for (int mt = 0; mt < 2; mt++)
#pragma unroll
                for (int half = 0; half < 2; half++)
#pragma unroll
                    for (int j = 0; j < 4; j++) sa[mt][half][j] = 0.0f;
#pragma unroll
            for (int ks = 0; ks < 4; ks++) {
                uint32_t k0, k1, k2, k3;
                LDSM4(k0, k1, k2, k3, sKb + SWZ((g*16 + brow)*128 + ks*32 + bcb));
                MMA16816(sa[0][0], qf[0][ks], k0, k1);
                MMA16816(sa[0][1], qf[0][ks], k2, k3);
                MMA16816(sa[1][0], qf[1][ks], k0, k1);
                MMA16816(sa[1][1], qf[1][ks], k2, k3);
            }

            // ── softmax: max (fp32), exp (bf16x2 SIMD) -> P frags, l via ones-MMA ──
            uint32_t pa[2][4];
#pragma unroll
            for (int mt = 0; mt < 2; mt++) {
                const float* s0 = sa[mt][0];
                const float* s1 = sa[mt][1];
                mac[mt][0] = fmaxf(mac[mt][0], fmaxf(fmaxf(s0[0], s0[1]), fmaxf(s1[0], s1[1])));
                mac[mt][1] = fmaxf(mac[mt][1], fmaxf(fmaxf(s0[2], s0[3]), fmaxf(s1[2], s1[3])));
                pa[mt][0] = exp_pair(pack_bf2(s0[0], s0[1]));
                pa[mt][1] = exp_pair(pack_bf2(s0[2], s0[3]));
                pa[mt][2] = exp_pair(pack_bf2(s1[0], s1[1]));
                pa[mt][3] = exp_pair(pack_bf2(s1[2], s1[3]));
                MMA16816(lC[mt], pa[mt], ONES, ONES);   // l += row-sums of P
            }

            // ── O += P·V, V frags shared across m-tiles ──
#pragma unroll
            for (int j = 0; j < 4; j++) {
                uint32_t v0, v1, v2, v3;
                LDSM4(v0, v1, v2, v3, sVb + SWZ((j*16 + brow)*128 + g*32 + bcb));
                MMA16816(of[0][2*j],   pa[0], v0, v1);
                MMA16816(of[0][2*j+1], pa[0], v2, v3);
                MMA16816(of[1][2*j],   pa[1], v0, v1);
                MMA16816(of[1][2*j+1], pa[1], v2, v3);
            }
        }
    }

    // ── epilogue ──
    const float keep = 1.0f - 0.3f / (1.0f + expf(-dropout_logits[h]));
    const int r = lane >> 2, cb = (lane & 3)*2;
    float cs = 0.0f;
#pragma unroll
    for (int mt = 0; mt < 2; mt++) {
        float l0 = lC[mt][0], l1 = lC[mt][2];
        float m0 = mac[mt][0], m1 = mac[mt][1];
        m0 = fmaxf(m0, __shfl_xor_sync(0xffffffffu, m0, 1));
        m0 = fmaxf(m0, __shfl_xor_sync(0xffffffffu, m0, 2));
        m1 = fmaxf(m1, __shfl_xor_sync(0xffffffffu, m1, 1));
        m1 = fmaxf(m1, __shfl_xor_sync(0xffffffffu, m1, 2));

        const float c0coef = keep / l0, c1coef = keep / l1;
        const int q = q0 + warp*32 + mt*16 + r;
        __nv_bfloat16* orowA = g_Ob + ((size_t)(b*NN + q    ))*CC + h*DD;
        __nv_bfloat16* orowB = g_Ob + ((size_t)(b*NN + q + 8))*CC + h*DD;
#pragma unroll
        for (int nt = 0; nt < 8; nt++) {
            *(uint32_t*)(orowA + nt*8 + cb) = pack_bf2(of[mt][nt][0]*c0coef, of[mt][nt][1]*c0coef);
            *(uint32_t*)(orowB + nt*8 + cb) = pack_bf2(of[mt][nt][2]*c1coef, of[mt][nt][3]*c1coef);
        }
        if ((lane & 3) == 0) cs += expp(m0)/l0 + expp(m1)/l1;
    }
#pragma unroll
    for (int off = 16; off > 0; off >>= 1)
        cs += __shfl_xor_sync(0xffffffffu, cs, off);
    if (lane == 0) atomicAdd(&g_conf[b], cs);
}

// ---------------------------------------------------------------------------
// Kernel 3: projection GEMM via HMMA, register-staged double-buffered pipeline.
// A = g_Ob (bf16 direct), B = proj_w (fp32, cvt). Unchanged from R15.
// ---------------------------------------------------------------------------
__global__ __launch_bounds__(256) void proj_kernel(const float* __restrict__ xin,
                                                   const float* __restrict__ pw,
                                                   const float* __restrict__ bias,
                                                   const float* __restrict__ resp,
                                                   float* __restrict__ out)
{
    __shared__ __align__(128) char smA[2][128*128];
    __shared__ __align__(128) char smB[2][64*128];
    const int t = threadIdx.x, warp = t >> 5, lane = t & 31;
    const int m0 = blockIdx.x * 128, c0 = blockIdx.y * 64;
    const uint32_t sA[2] = { smem_u32(smA[0]), smem_u32(smA[1]) };
    const uint32_t sB[2] = { smem_u32(smB[0]), smem_u32(smB[1]) };
    const int lr = lane & 7, mm = lane >> 3;

    const int arw[4] = { (t      ) >> 3, (t + 256) >> 3, (t + 512) >> 3, (t + 768) >> 3 };
    const int ajj    = (t & 7) * 8;
    const uint32_t asw[4] = { (uint32_t)SWZ(arw[0]*128 + (t&7)*16), (uint32_t)SWZ(arw[1]*128 + (t&7)*16),
                              (uint32_t)SWZ(arw[2]*128 + (t&7)*16), (uint32_t)SWZ(arw[3]*128 + (t&7)*16) };
    const int brw[2] = { (t      ) >> 3, (t + 256) >> 3 };
    const uint32_t bsw[2] = { asw[0], asw[1] };

    float of[8][4];
#pragma unroll
    for (int i = 0; i < 8; i++)
#pragma unroll
        for (int j = 0; j < 4; j++) of[i][j] = 0.0f;

    const int arow = warp*16 + (mm & 1)*8 + lr, acb = (mm >> 1)*16;
    const int brow = (mm >> 1)*8 + lr,          bcb = (mm & 1)*16;

    // preload chunk 0 -> buf 0
    {
        uint4 stA[4], stB[2];
#pragma unroll
        for (int s = 0; s < 4; s++) stA[s] = *(const uint4*)(g_Ob + (size_t)(m0 + arw[s])*192 + ajj);
#pragma unroll
        for (int s = 0; s < 2; s++) stB[s] = cvt8_bf16(pw + (size_t)(c0 + brw[s])*192 + ajj);
#pragma unroll
        for (int s = 0; s < 4; s++) *(uint4*)(smA[0] + asw[s]) = stA[s];
#pragma unroll
        for (int s = 0; s < 2; s++) *(uint4*)(smB[0] + bsw[s]) = stB[s];
    }
    __syncthreads();

    for (int chunk = 0; chunk < 3; chunk++) {
        const int buf = chunk & 1;
        uint4 stA[4], stB[2];
        if (chunk < 2) {
            const int k1 = (chunk + 1) * 64;
#pragma unroll
            for (int s = 0; s < 4; s++) stA[s] = *(const uint4*)(g_Ob + (size_t)(m0 + arw[s])*192 + k1 + ajj);
#pragma unroll
            for (int s = 0; s < 2; s++) stB[s] = cvt8_bf16(pw + (size_t)(c0 + brw[s])*192 + k1 + ajj);
        }

        uint32_t af[4][4];
#pragma unroll
        for (int ks = 0; ks < 4; ks++)
            LDSM4(af[ks][0], af[ks][1], af[ks][2], af[ks][3],
                  sA[buf] + SWZ(arow*128 + ks*32 + acb));
#pragma unroll
        for (int g = 0; g < 4; g++) {
#pragma unroll
            for (int ks = 0; ks < 4; ks++) {
                uint32_t b0, b1, b2, b3;
                LDSM4(b0, b1, b2, b3, sB[buf] + SWZ((g*16 + brow)*128 + ks*32 + bcb));
                MMA16816(of[2*g],   af[ks], b0, b1);
                MMA16816(of[2*g+1], af[ks], b2, b3);
            }
        }

        if (chunk < 2) {
#pragma unroll
            for (int s = 0; s < 4; s++) *(uint4*)(smA[buf ^ 1] + asw[s]) = stA[s];
#pragma unroll
            for (int s = 0; s < 2; s++) *(uint4*)(smB[buf ^ 1] + bsw[s]) = stB[s];
            __syncthreads();
        }
    }

    const float wr = 1.0f / (1.0f + expf(-resp[0]));
    const float onemw = 1.0f - wr;
    const int r = lane >> 2, cb = (lane & 3)*2;
    const int mA = m0 + warp*16 + r;

#pragma unroll
    for (int nt = 0; nt < 8; nt++) {
        const int c = c0 + nt*8 + cb;
        float bz0 = bias[c], bz1 = bias[c+1];
        float2 xa = *(const float2*)(xin + (size_t)mA*192 + c);
        float2 xb = *(const float2*)(xin + (size_t)(mA+8)*192 + c);
        float2 oa = { wr*(of[nt][0] + bz0) + onemw*xa.x,
                      wr*(of[nt][1] + bz1) + onemw*xa.y };
        float2 ob = { wr*(of[nt][2] + bz0) + onemw*xb.x,
                      wr*(of[nt][3] + bz1) + onemw*xb.y };
        *(float2*)(out + (size_t)mA*192 + c)     = oa;
        *(float2*)(out + (size_t)(mA+8)*192 + c) = ob;
    }

    if (blockIdx.x == 0 && blockIdx.y == 0 && t < BB)
        out[(size_t)BB*NN*CC + t] = g_conf[t] * (1.0f / (HH * NN));
}

// ---------------------------------------------------------------------------
extern "C" void kernel_launch(void* const* d_in, const int* in_sizes, int n_in,
                              void* d_out, int out_size)
{
    const float* x    = (const float*)d_in[0];
    const float* qw   = (const float*)d_in[1];
    const float* qb   = (const float*)d_in[2];
    const float* pw   = (const float*)d_in[3];
    const float* pb   = (const float*)d_in[4];
    const float* temp = (const float*)d_in[5];
    const float* dl   = (const float*)d_in[6];
    const float* rp   = (const float*)d_in[7];
    const float* tau  = (const float*)d_in[8];
    float* out = (float*)d_out;

    // host-side attribute set (idempotent; not a stream op; no allocation)
    cudaFuncSetAttribute(qkv_kernel, cudaFuncAttributeMaxDynamicSharedMemorySize, 98304);

    qkv_kernel<<<BB*NN/128, 256, 98304>>>(x, qw, qb, temp, tau);   // 256 CTAs

    dim3 ga(NN/128, HH, BB);           // 8 x 3 x 32
    attn_kernel<<<ga, 128>>>(dl);

    dim3 gp(BB*NN/128, CC/64);         // 256 x 3
    proj_kernel<<<gp, 256>>>(x, pw, pb, rp, out);
}

// round 17
// speedup vs baseline: 1.5962x; 1.5962x over previous
#include <cuda_runtime.h>
#include <cuda_bf16.h>
#include <math.h>
#include <cstdint>

#define BB 32
#define NN 1024
#define CC 192
#define HH 3
#define DD 64

// Scratch (device globals — allocation-free)
__device__ __align__(16) __nv_bfloat16 g_Xb [BB*NN*CC];     // x bf16
__device__ __align__(16) __nv_bfloat16 g_Wqb[3*CC*CC];      // qkv_w bf16
__device__ __align__(16) __nv_bfloat16 g_Wpb[CC*CC];        // proj_w bf16
__device__ __align__(16) __nv_bfloat16 g_Qb [BB*HH*NN*DD];  // [bh][n][d], pre-scaled by 0.125/tau(b,h)
__device__ __align__(16) __nv_bfloat16 g_Kb [BB*HH*NN*DD];  // [bh][n][d]
__device__ __align__(16) __nv_bfloat16 g_Vtb[BB*HH*DD*NN];  // [bh][d][n]
__device__ __align__(16) __nv_bfloat16 g_Ob [BB*NN*CC];     // attn out bf16
__device__ float g_conf[BB];

// ───────────────────────── helpers ─────────────────────────
__device__ __forceinline__ uint32_t smem_u32(const void* p) {
    uint32_t a;
    asm("{ .reg .u64 t; cvta.to.shared.u64 t, %1; cvt.u32.u64 %0, t; }" : "=r"(a) : "l"(p));
    return a;
}
#define SWZ(o) ((o) ^ (((o) >> 3) & 0x70))

#define LDSM4(r0, r1, r2, r3, addr)                                              \
    asm volatile("ldmatrix.sync.aligned.m8n8.x4.shared.b16 {%0,%1,%2,%3}, [%4];" \
        : "=r"(r0), "=r"(r1), "=r"(r2), "=r"(r3) : "r"(addr))

#define MMA16816(d, a, b0, b1)                                                   \
    asm volatile("mma.sync.aligned.m16n8k16.row.col.f32.bf16.bf16.f32 "          \
        "{%0,%1,%2,%3}, {%4,%5,%6,%7}, {%8,%9}, {%0,%1,%2,%3};"                  \
        : "+f"((d)[0]), "+f"((d)[1]), "+f"((d)[2]), "+f"((d)[3])                 \
        : "r"((a)[0]), "r"((a)[1]), "r"((a)[2]), "r"((a)[3]), "r"(b0), "r"(b1))

__device__ __forceinline__ void cp16(uint32_t smaddr, const void* g) {
    asm volatile("cp.async.cg.shared.global [%0], [%1], 16;" :: "r"(smaddr), "l"(g));
}
#define CP_COMMIT() asm volatile("cp.async.commit_group;" ::: "memory")
#define CP_WAIT0()  asm volatile("cp.async.wait_group 0;" ::: "memory")

// pack (lo, hi) -> bf16x2
__device__ __forceinline__ uint32_t pack_bf2(float lo, float hi) {
    uint32_t r;
    asm("cvt.rn.satfinite.bf16x2.f32 %0, %1, %2;" : "=r"(r) : "f"(hi), "f"(lo));
    return r;
}

// 5th-order Taylor exp (fp32) — for the confidence numerator only
__device__ __forceinline__ float expp(float x) {
    float t = fmaf(x, 8.3333333e-3f, 4.1666667e-2f);
    t = fmaf(x, t, 1.6666667e-1f);
    t = fmaf(x, t, 0.5f);
    t = fmaf(x, t, 1.0f);
    t = fmaf(x, t, 1.0f);
    return t;
}

// 4th-order Taylor exp on a bf16x2 pair (|x| <~ 0.5).
#define K_1_24 0x3D2B3D2Bu
#define K_1_6  0x3E2B3E2Bu
#define K_HALF 0x3F003F00u
#define K_ONE  0x3F803F80u
__device__ __forceinline__ uint32_t exp_pair(uint32_t x) {
    uint32_t t;
    const uint32_t k24 = K_1_24, k6 = K_1_6, kh = K_HALF, k1 = K_ONE;
    asm("fma.rn.bf16x2 %0, %1, %2, %3;" : "=r"(t) : "r"(x), "r"(k24), "r"(k6));
    asm("fma.rn.bf16x2 %0, %1, %2, %3;" : "=r"(t) : "r"(x), "r"(t), "r"(kh));
    asm("fma.rn.bf16x2 %0, %1, %2, %3;" : "=r"(t) : "r"(x), "r"(t), "r"(k1));
    asm("fma.rn.bf16x2 %0, %1, %2, %3;" : "=r"(t) : "r"(x), "r"(t), "r"(k1));
    return t;
}

// ---------------------------------------------------------------------------
// Kernel 0: fp32 -> bf16 conversion for x, qkv_w, proj_w; zero g_conf.
// ---------------------------------------------------------------------------
__global__ __launch_bounds__(256) void convert_kernel(const float* __restrict__ x,
                                                      const float* __restrict__ qw,
                                                      const float* __restrict__ pw)
{
    const int tid = blockIdx.x * 256 + threadIdx.x;
    const int stride = gridDim.x * 256;
    const int NX = BB*NN*CC/4;       // 1,572,864
    for (int i = tid; i < NX; i += stride) {
        float4 v = ((const float4*)x)[i];
        uint2 o = { pack_bf2(v.x, v.y), pack_bf2(v.z, v.w) };
        ((uint2*)g_Xb)[i] = o;
    }
    const int NQ = 3*CC*CC/4;        // 27,648
    for (int i = tid; i < NQ; i += stride) {
        float4 v = ((const float4*)qw)[i];
        uint2 o = { pack_bf2(v.x, v.y), pack_bf2(v.z, v.w) };
        ((uint2*)g_Wqb)[i] = o;
    }
    const int NP = CC*CC/4;          // 9,216
    for (int i = tid; i < NP; i += stride) {
        float4 v = ((const float4*)pw)[i];
        uint2 o = { pack_bf2(v.x, v.y), pack_bf2(v.z, v.w) };
        ((uint2*)g_Wpb)[i] = o;
    }
    if (tid < BB) g_conf[tid] = 0.0f;
}

// ---------------------------------------------------------------------------
// Kernel 1: QKV GEMM via HMMA, cp.async double-buffered pipeline (bf16 A/B).
// CTA tile 128x64, 3 K-chunks, 1 sync/chunk. Scatter to bf16 Q/K/V^T.
// SMEM: 2 x (A 16KB + B 8KB) = 48KB static.
// ---------------------------------------------------------------------------
__global__ __launch_bounds__(256) void qkv_kernel(const float* __restrict__ bias,
                                                  const float* __restrict__ temp_param,
                                                  const float* __restrict__ tau_al)
{
    __shared__ __align__(128) char smA[2][128*128];
    __shared__ __align__(128) char smB[2][64*128];
    const int t = threadIdx.x, warp = t >> 5, lane = t & 31;
    const int m0 = blockIdx.x * 128, c0 = blockIdx.y * 64;
    const uint32_t sA[2] = { smem_u32(smA[0]), smem_u32(smA[1]) };
    const uint32_t sB[2] = { smem_u32(smB[0]), smem_u32(smB[1]) };
    const int lr = lane & 7, mm = lane >> 3;

    // per-thread cp.async coordinates
    const int prow = t >> 3, pj = t & 7;                 // base unit
    const uint32_t psw = (uint32_t)SWZ(prow*128 + pj*16);

    // prefetch chunk 0 -> buf 0  (A: 4 units, B: 2 units per thread)
#pragma unroll
    for (int s = 0; s < 4; s++) {
        int u = t + s*256, row = u >> 3, j = u & 7;
        cp16(sA[0] + SWZ(row*128 + j*16), g_Xb + (size_t)(m0 + row)*192 + j*8);
    }
#pragma unroll
    for (int s = 0; s < 2; s++) {
        int u = t + s*256, row = u >> 3, j = u & 7;
        cp16(sB[0] + SWZ(row*128 + j*16), g_Wqb + (size_t)(c0 + row)*192 + j*8);
    }
    CP_COMMIT();

    float of[8][4];
#pragma unroll
    for (int i = 0; i < 8; i++)
#pragma unroll
        for (int j = 0; j < 4; j++) of[i][j] = 0.0f;

    const int arow = warp*16 + (mm & 1)*8 + lr, acb = (mm >> 1)*16;
    const int brow = (mm >> 1)*8 + lr,          bcb = (mm & 1)*16;

    for (int chunk = 0; chunk < 3; chunk++) {
        const int buf = chunk & 1;
        CP_WAIT0();
        __syncthreads();   // data for `chunk` ready; all reads of buf^1 done

        if (chunk < 2) {   // prefetch chunk+1 into the other buffer
            const int k1 = (chunk + 1) * 64;
#pragma unroll
            for (int s = 0; s < 4; s++) {
                int u = t + s*256, row = u >> 3, j = u & 7;
                cp16(sA[buf ^ 1] + SWZ(row*128 + j*16), g_Xb + (size_t)(m0 + row)*192 + k1 + j*8);
            }
#pragma unroll
            for (int s = 0; s < 2; s++) {
                int u = t + s*256, row = u >> 3, j = u & 7;
                cp16(sB[buf ^ 1] + SWZ(row*128 + j*16), g_Wqb + (size_t)(c0 + row)*192 + k1 + j*8);
            }
            CP_COMMIT();
        }

        uint32_t af[4][4];
#pragma unroll
        for (int ks = 0; ks < 4; ks++)
            LDSM4(af[ks][0], af[ks][1], af[ks][2], af[ks][3],
                  sA[buf] + SWZ(arow*128 + ks*32 + acb));
#pragma unroll
        for (int g = 0; g < 4; g++) {
#pragma unroll
            for (int ks = 0; ks < 4; ks++) {
                uint32_t b0, b1, b2, b3;
                LDSM4(b0, b1, b2, b3, sB[buf] + SWZ((g*16 + brow)*128 + ks*32 + bcb));
                MMA16816(of[2*g],   af[ks], b0, b1);
                MMA16816(of[2*g+1], af[ks], b2, b3);
            }
        }
    }

    // epilogue: bias, convert bf16, scatter to Q (scaled) / K / V^T
    const int jj = c0 / 192;                 // 0=q,1=k,2=v (64-wide tiles align)
    const int h  = (c0 - jj*192) >> 6;
    const int r = lane >> 2, cb = (lane & 3)*2;
    const int mA = m0 + warp*16 + r;         // rows mA and mA+8 (same batch b)
    const int b = mA >> 10, n = mA & 1023;
    const int bh = b*HH + h;

    float scq = 1.0f;
    if (jj == 0) {
        float tp  = temp_param[h];
        float tau = tau_al[b*HH + h] + (0.1f + log1pf(expf(tp))) * 1.5f;
        scq = 0.125f / tau;
    }

#pragma unroll
    for (int nt = 0; nt < 8; nt++) {
        const int d = nt*8 + cb;
        float bz0 = bias[c0 + d], bz1 = bias[c0 + d + 1];
        float v0 = of[nt][0] + bz0, v1 = of[nt][1] + bz1;   // row mA
        float v2 = of[nt][2] + bz0, v3 = of[nt][3] + bz1;   // row mA+8
        if (jj == 0) {
            *(uint32_t*)(g_Qb + ((size_t)(bh<<10) + n    )*64 + d) = pack_bf2(v0*scq, v1*scq);
            *(uint32_t*)(g_Qb + ((size_t)(bh<<10) + n + 8)*64 + d) = pack_bf2(v2*scq, v3*scq);
        } else if (jj == 1) {
            *(uint32_t*)(g_Kb + ((size_t)(bh<<10) + n    )*64 + d) = pack_bf2(v0, v1);
            *(uint32_t*)(g_Kb + ((size_t)(bh<<10) + n + 8)*64 + d) = pack_bf2(v2, v3);
        } else {
            __nv_bfloat16* Vt = g_Vtb + ((size_t)bh << 16);
            Vt[((size_t)(d  )<<10) + n    ] = __float2bfloat16(v0);
            Vt[((size_t)(d+1)<<10) + n    ] = __float2bfloat16(v1);
            Vt[((size_t)(d  )<<10) + n + 8] = __float2bfloat16(v2);
            Vt[((size_t)(d+1)<<10) + n + 8] = __float2bfloat16(v3);
        }
    }
}

// ---------------------------------------------------------------------------
// Kernel 2: flash attention, M=32/warp (4 warps, 128 thr), bf16x2 SIMD softmax.
// 3 CTAs/SM. Unchanged from R13/R15 (best measured config).
// ---------------------------------------------------------------------------
__global__ __launch_bounds__(128, 3) void attn_kernel(const float* __restrict__ dropout_logits)
{
    __shared__ __align__(128) char smQ[128*128];
    __shared__ __align__(128) char smK[2][64*128];
    __shared__ __align__(128) char smV[2][64*128];

    const int t = threadIdx.x, warp = t >> 5, lane = t & 31;
    const int b = blockIdx.z, h = blockIdx.y, q0 = blockIdx.x * 128;
    const int bh = b*HH + h;
    const uint32_t sQ = smem_u32(smQ);
    const uint32_t sK[2] = { smem_u32(smK[0]), smem_u32(smK[1]) };
    const uint32_t sV[2] = { smem_u32(smV[0]), smem_u32(smV[1]) };

    const __nv_bfloat16* Qbh  = g_Qb  + (size_t)bh * NN * DD;
    const __nv_bfloat16* Kbh  = g_Kb  + (size_t)bh * NN * DD;
    const __nv_bfloat16* Vtbh = g_Vtb + (size_t)bh * DD * NN;

    // prefetch chunk 0 into buffer 0
#pragma unroll
    for (int s = 0; s < 4; s++) {
        int idx = t + s*128, row = idx >> 3, j = idx & 7;
        cp16(sK[0] + SWZ(row*128 + j*16), Kbh  + (size_t)row*64 + j*8);
        cp16(sV[0] + SWZ(row*128 + j*16), Vtbh + (size_t)row*NN + j*8);
    }
    CP_COMMIT();

    // Q tile [128 x 64] bf16 -> swizzled smem (plain loads)
#pragma unroll
    for (int i = t; i < 1024; i += 128) {
        int row = i >> 3, j = i & 7;
        *(uint4*)(smQ + SWZ(row*128 + j*16)) = *(const uint4*)(Qbh + (size_t)(q0 + row)*64 + j*8);
    }
    __syncthreads();

    const int lr = lane & 7, mm = lane >> 3;
    uint32_t qf[2][4][4];
#pragma unroll
    for (int mt = 0; mt < 2; mt++) {
        const int qrow = warp*32 + mt*16 + (mm & 1)*8 + lr;
        const int qcb  = (mm >> 1)*16;
#pragma unroll
        for (int ks = 0; ks < 4; ks++)
            LDSM4(qf[mt][ks][0], qf[mt][ks][1], qf[mt][ks][2], qf[mt][ks][3],
                  sQ + SWZ(qrow*128 + ks*32 + qcb));
    }

    float of[2][8][4];
#pragma unroll
    for (int mt = 0; mt < 2; mt++)
#pragma unroll
        for (int i = 0; i < 8; i++)
#pragma unroll
            for (int j = 0; j < 4; j++) of[mt][i][j] = 0.0f;
    float lC[2][4];                       // ones-MMA accumulator: row sums of P
#pragma unroll
    for (int mt = 0; mt < 2; mt++)
#pragma unroll
        for (int j = 0; j < 4; j++) lC[mt][j] = 0.0f;
    float mac[2][2] = {{-1e30f,-1e30f},{-1e30f,-1e30f}};

    const int brow = (mm >> 1)*8 + lr;
    const int bcb  = (mm & 1)*16;
    const uint32_t ONES = K_ONE;          // bf16x2 {1.0, 1.0}

    for (int kc = 0; kc < 16; kc++) {
        const int buf = kc & 1;
        CP_WAIT0();
        __syncthreads();

        if (kc < 15) {
            const int n1 = (kc + 1) * 64;
            const uint32_t kb = sK[buf ^ 1], vb = sV[buf ^ 1];
#pragma unroll
            for (int s = 0; s < 4; s++) {
                int idx = t + s*128, row = idx >> 3, j = idx & 7;
                cp16(kb + SWZ(row*128 + j*16), Kbh  + (size_t)(n1 + row)*64 + j*8);
                cp16(vb + SWZ(row*128 + j*16), Vtbh + (size_t)row*NN + n1 + j*8);
            }
            CP_COMMIT();
        }

        const uint32_t sKb = sK[buf], sVb = sV[buf];
#pragma unroll
        for (int g = 0; g < 4; g++) {
            // ── S = Q·K^T (logits pre-scaled), K frags shared across m-tiles ──
            float sa[2][2][4];
#pragma unroll
            for (int mt = 0; mt < 2; mt++)
#pragma unroll
                for (int half = 0; half < 2; half++)
#pragma unroll
                    for (int j = 0; j < 4; j++) sa[mt][half][j] = 0.0f;
#pragma unroll
            for (int ks = 0; ks < 4; ks++) {
                uint32_t k0, k1, k2, k3;
                LDSM4(k0, k1, k2, k3, sKb + SWZ((g*16 + brow)*128 + ks*32 + bcb));
                MMA16816(sa[0][0], qf[0][ks], k0, k1);
                MMA16816(sa[0][1], qf[0][ks], k2, k3);
                MMA16816(sa[1][0], qf[1][ks], k0, k1);
                MMA16816(sa[1][1], qf[1][ks], k2, k3);
            }

            // ── softmax: max (fp32), exp (bf16x2 SIMD) -> P frags, l via ones-MMA ──
            uint32_t pa[2][4];
#pragma unroll
            for (int mt = 0; mt < 2; mt++) {
                const float* s0 = sa[mt][0];
                const float* s1 = sa[mt][1];
                mac[mt][0] = fmaxf(mac[mt][0], fmaxf(fmaxf(s0[0], s0[1]), fmaxf(s1[0], s1[1])));
                mac[mt][1] = fmaxf(mac[mt][1], fmaxf(fmaxf(s0[2], s0[3]), fmaxf(s1[2], s1[3])));
                pa[mt][0] = exp_pair(pack_bf2(s0[0], s0[1]));
                pa[mt][1] = exp_pair(pack_bf2(s0[2], s0[3]));
                pa[mt][2] = exp_pair(pack_bf2(s1[0], s1[1]));
                pa[mt][3] = exp_pair(pack_bf2(s1[2], s1[3]));
                MMA16816(lC[mt], pa[mt], ONES, ONES);   // l += row-sums of P
            }

            // ── O += P·V, V frags shared across m-tiles ──
#pragma unroll
            for (int j = 0; j < 4; j++) {
                uint32_t v0, v1, v2, v3;
                LDSM4(v0, v1, v2, v3, sVb + SWZ((j*16 + brow)*128 + g*32 + bcb));
                MMA16816(of[0][2*j],   pa[0], v0, v1);
                MMA16816(of[0][2*j+1], pa[0], v2, v3);
                MMA16816(of[1][2*j],   pa[1], v0, v1);
                MMA16816(of[1][2*j+1], pa[1], v2, v3);
            }
        }
    }

    // ── epilogue ──
    const float keep = 1.0f - 0.3f / (1.0f + expf(-dropout_logits[h]));
    const int r = lane >> 2, cb = (lane & 3)*2;
    float cs = 0.0f;
#pragma unroll
    for (int mt = 0; mt < 2; mt++) {
        float l0 = lC[mt][0], l1 = lC[mt][2];
        float m0 = mac[mt][0], m1 = mac[mt][1];
        m0 = fmaxf(m0, __shfl_xor_sync(0xffffffffu, m0, 1));
        m0 = fmaxf(m0, __shfl_xor_sync(0xffffffffu, m0, 2));
        m1 = fmaxf(m1, __shfl_xor_sync(0xffffffffu, m1, 1));
        m1 = fmaxf(m1, __shfl_xor_sync(0xffffffffu, m1, 2));

        const float c0coef = keep / l0, c1coef = keep / l1;
        const int q = q0 + warp*32 + mt*16 + r;
        __nv_bfloat16* orowA = g_Ob + ((size_t)(b*NN + q    ))*CC + h*DD;
        __nv_bfloat16* orowB = g_Ob + ((size_t)(b*NN + q + 8))*CC + h*DD;
#pragma unroll
        for (int nt = 0; nt < 8; nt++) {
            *(uint32_t*)(orowA + nt*8 + cb) = pack_bf2(of[mt][nt][0]*c0coef, of[mt][nt][1]*c0coef);
            *(uint32_t*)(orowB + nt*8 + cb) = pack_bf2(of[mt][nt][2]*c1coef, of[mt][nt][3]*c1coef);
        }
        if ((lane & 3) == 0) cs += expp(m0)/l0 + expp(m1)/l1;
    }
#pragma unroll
    for (int off = 16; off > 0; off >>= 1)
        cs += __shfl_xor_sync(0xffffffffu, cs, off);
    if (lane == 0) atomicAdd(&g_conf[b], cs);
}

// ---------------------------------------------------------------------------
// Kernel 3: projection GEMM via HMMA, cp.async double-buffered pipeline.
// A = g_Ob (bf16), B = g_Wpb (bf16). Residual blend + confidence.
// ---------------------------------------------------------------------------
__global__ __launch_bounds__(256) void proj_kernel(const float* __restrict__ xin,
                                                   const float* __restrict__ bias,
                                                   const float* __restrict__ resp,
                                                   float* __restrict__ out)
{
    __shared__ __align__(128) char smA[2][128*128];
    __shared__ __align__(128) char smB[2][64*128];
    const int t = threadIdx.x, warp = t >> 5, lane = t & 31;
    const int m0 = blockIdx.x * 128, c0 = blockIdx.y * 64;
    const uint32_t sA[2] = { smem_u32(smA[0]), smem_u32(smA[1]) };
    const uint32_t sB[2] = { smem_u32(smB[0]), smem_u32(smB[1]) };
    const int lr = lane & 7, mm = lane >> 3;

    // prefetch chunk 0 -> buf 0
#pragma unroll
    for (int s = 0; s < 4; s++) {
        int u = t + s*256, row = u >> 3, j = u & 7;
        cp16(sA[0] + SWZ(row*128 + j*16), g_Ob + (size_t)(m0 + row)*192 + j*8);
    }
#pragma unroll
    for (int s = 0; s < 2; s++) {
        int u = t + s*256, row = u >> 3, j = u & 7;
        cp16(sB[0] + SWZ(row*128 + j*16), g_Wpb + (size_t)(c0 + row)*192 + j*8);
    }
    CP_COMMIT();

    float of[8][4];
#pragma unroll
    for (int i = 0; i < 8; i++)
#pragma unroll
        for (int j = 0; j < 4; j++) of[i][j] = 0.0f;

    const int arow = warp*16 + (mm & 1)*8 + lr, acb = (mm >> 1)*16;
    const int brow = (mm >> 1)*8 + lr,          bcb = (mm & 1)*16;

    for (int chunk = 0; chunk < 3; chunk++) {
        const int buf = chunk & 1;
        CP_WAIT0();
        __syncthreads();

        if (chunk < 2) {
            const int k1 = (chunk + 1) * 64;
#pragma unroll
            for (int s = 0; s < 4; s++) {
                int u = t + s*256, row = u >> 3, j = u & 7;
                cp16(sA[buf ^ 1] + SWZ(row*128 + j*16), g_Ob + (size_t)(m0 + row)*192 + k1 + j*8);
            }
#pragma unroll
            for (int s = 0; s < 2; s++) {
                int u = t + s*256, row = u >> 3, j = u & 7;
                cp16(sB[buf ^ 1] + SWZ(row*128 + j*16), g_Wpb + (size_t)(c0 + row)*192 + k1 + j*8);
            }
            CP_COMMIT();
        }

        uint32_t af[4][4];
#pragma unroll
        for (int ks = 0; ks < 4; ks++)
            LDSM4(af[ks][0], af[ks][1], af[ks][2], af[ks][3],
                  sA[buf] + SWZ(arow*128 + ks*32 + acb));
#pragma unroll
        for (int g = 0; g < 4; g++) {
#pragma unroll
            for (int ks = 0; ks < 4; ks++) {
                uint32_t b0, b1, b2, b3;
                LDSM4(b0, b1, b2, b3, sB[buf] + SWZ((g*16 + brow)*128 + ks*32 + bcb));
                MMA16816(of[2*g],   af[ks], b0, b1);
                MMA16816(of[2*g+1], af[ks], b2, b3);
            }
        }
    }

    const float wr = 1.0f / (1.0f + expf(-resp[0]));
    const float onemw = 1.0f - wr;
    const int r = lane >> 2, cb = (lane & 3)*2;
    const int mA = m0 + warp*16 + r;

#pragma unroll
    for (int nt = 0; nt < 8; nt++) {
        const int c = c0 + nt*8 + cb;
        float bz0 = bias[c], bz1 = bias[c+1];
        float2 xa = *(const float2*)(xin + (size_t)mA*192 + c);
        float2 xb = *(const float2*)(xin + (size_t)(mA+8)*192 + c);
        float2 oa = { wr*(of[nt][0] + bz0) + onemw*xa.x,
                      wr*(of[nt][1] + bz1) + onemw*xa.y };
        float2 ob = { wr*(of[nt][2] + bz0) + onemw*xb.x,
                      wr*(of[nt][3] + bz1) + onemw*xb.y };
        *(float2*)(out + (size_t)mA*192 + c)     = oa;
        *(float2*)(out + (size_t)(mA+8)*192 + c) = ob;
    }

    if (blockIdx.x == 0 && blockIdx.y == 0 && t < BB)
        out[(size_t)BB*NN*CC + t] = g_conf[t] * (1.0f / (HH * NN));
}

// ---------------------------------------------------------------------------
extern "C" void kernel_launch(void* const* d_in, const int* in_sizes, int n_in,
                              void* d_out, int out_size)
{
    const float* x    = (const float*)d_in[0];
    const float* qw   = (const float*)d_in[1];
    const float* qb   = (const float*)d_in[2];
    const float* pw   = (const float*)d_in[3];
    const float* pb   = (const float*)d_in[4];
    const float* temp = (const float*)d_in[5];
    const float* dl   = (const float*)d_in[6];
    const float* rp   = (const float*)d_in[7];
    const float* tau  = (const float*)d_in[8];
    float* out = (float*)d_out;

    convert_kernel<<<592, 256>>>(x, qw, pw);

    dim3 gq(BB*NN/128, (3*CC)/64);     // 256 x 9
    qkv_kernel<<<gq, 256>>>(qb, temp, tau);

    dim3 ga(NN/128, HH, BB);           // 8 x 3 x 32
    attn_kernel<<<ga, 128>>>(dl);

    dim3 gp(BB*NN/128, CC/64);         // 256 x 3
    proj_kernel<<<gp, 256>>>(x, pb, rp, out);
}